// round 7
// baseline (speedup 1.0000x reference)
#include <cuda_runtime.h>

// DynamicMaskHead fused kernel for GB300 (sm_103a), round 7.
// Base = round 5 (64.3us: 400 blocks, one wave at 3 CTA/SM, LDS.128 weights,
// 6-LDS phase-2 stencil). R6's restructures regressed (longer dep chains);
// reverted. R7 keeps R5's structure and only removes instructions:
//  - biases folded into the first FMA of each layer (no 32-mov inits)
//  - layer-2 weights/bias pre-scaled 0.5 -> smem half-logits -> sigmoid
//    needs no inner 0.5 multiply
//  - dead (ox4==0) select removed (cm1 clamp already makes A==B there)

#define HH       96
#define WW       160
#define HW       15360
#define OWw      320
#define NP       169
#define NTHREADS 256
#define QW       (WW / 4)

// Repacked weight layout (floats, 16B-aligned base):
//   [0,96)    l0w: 8 ch x 12 (10 weights + 2 pad)
//   [96,104)  l0b: 8
//   [104,168) l1w: 8 ch x 8
//   [168,176) l1b: 8
//   [176,184) l2w: 8   (pre-scaled by 0.5)
//   [184]     l2b      (pre-scaled by 0.5)
#define SW_FLOATS 188
#define SMEM_FLOATS (HW + SW_FLOATS)

// x = 0.5 * logit: sigmoid(L) = 0.5*tanh(0.5L) + 0.5
__device__ __forceinline__ float sig_h(float x) {
    float t;
    asm("tanh.approx.f32 %0, %1;" : "=f"(t) : "f"(x));
    return fmaf(0.5f, t, 0.5f);
}

__global__ __launch_bounds__(NTHREADS, 3)
void dmh_kernel(const float* __restrict__ feats,     // [2, 8, 96, 160]
                const float* __restrict__ p1,        // [N, 169]
                const float* __restrict__ p2,        // [N, 169]
                const float* __restrict__ loc,       // [N, 2]
                const float* __restrict__ off,       // [N, 2]
                const int*   __restrict__ imi,       // [N]
                const int*   __restrict__ fpn,       // [N]
                float*       __restrict__ out)       // [2, N, 192, 320]
{
    extern __shared__ float smem[];
    float* sL = smem;           // [HW] half-logits
    float* sw = smem + HW;      // [SW_FLOATS]

    const int tid    = threadIdx.x;
    const int inst   = blockIdx.x;
    const int head   = blockIdx.y;
    const int n_inst = gridDim.x;

    // ---- Load + repack params (layer-2 pre-scaled by 0.5) ----
    const float* params = (head == 0 ? p1 : p2) + inst * NP;
    if (tid < NP) {
        float w = params[tid];
        int d;
        if      (tid < 80)  { const int c = tid / 10; d = c * 12 + (tid - c * 10); }
        else if (tid < 144) { d = 104 + (tid - 80); }
        else if (tid < 152) { d = 176 + (tid - 144); w *= 0.5f; }
        else if (tid < 160) { d = 96  + (tid - 152); }
        else if (tid < 168) { d = 168 + (tid - 160); }
        else                { d = 184; w *= 0.5f; }
        sw[d] = w;
    }
    if (tid >= 200 && tid < 208) {
        const int c = tid - 200;
        sw[c * 12 + 10] = 0.0f;
        sw[c * 12 + 11] = 0.0f;
    }

    const int   lvl     = fpn[inst];
    const float inv_soi = 1.0f / (64.0f * (float)(1 << lvl));
    float lx = loc[2 * inst + 0];
    float ly = loc[2 * inst + 1];
    if (head) {
        lx += off[2 * inst + 0] * 128.0f;
        ly += off[2 * inst + 1] * 128.0f;
    }
    const float* fb = feats + (size_t)imi[inst] * (8 * HW);
    const float dx = -8.0f * inv_soi;
    __syncthreads();

    // ---------------- Phase 1: MLP, 4 px/thread/iter, 15 iters --------------
    #pragma unroll 1
    for (int q = tid; q < HW / 4; q += NTHREADS) {
        const int row  = q / QW;
        const int px0  = (q - row * QW) * 4;
        const int base = row * WW + px0;

        const float cy  = (ly - (float)(row * 8 + 4)) * inv_soi;
        const float cx0 = (lx - (float)(px0 * 8 + 4)) * inv_soi;
        const float cx[4] = { cx0, cx0 + dx, cx0 + 2.0f * dx, cx0 + 3.0f * dx };

        float4 v[8];
        #pragma unroll
        for (int j = 0; j < 8; ++j)
            v[j] = *reinterpret_cast<const float4*>(fb + j * HW + base);

        // Layer 0: bias folded into the coord FMA (parallel per-k form).
        float a[8][4];
        const float4 b0A = *reinterpret_cast<const float4*>(sw + 96);
        const float4 b0B = *reinterpret_cast<const float4*>(sw + 100);
        const float b0v[8] = { b0A.x, b0A.y, b0A.z, b0A.w, b0B.x, b0B.y, b0B.z, b0B.w };
        #pragma unroll
        for (int c = 0; c < 8; ++c) {
            const float4 wA = *reinterpret_cast<const float4*>(sw + c * 12);
            const float4 wB = *reinterpret_cast<const float4*>(sw + c * 12 + 4);
            const float2 wC = *reinterpret_cast<const float2*>(sw + c * 12 + 8);
            #pragma unroll
            for (int k = 0; k < 4; ++k) {
                float u = fmaf(wA.x, cx[k], fmaf(wA.y, cy, b0v[c]));
                u = fmaf(wA.z, (&v[0].x)[k], u);
                u = fmaf(wA.w, (&v[1].x)[k], u);
                u = fmaf(wB.x, (&v[2].x)[k], u);
                u = fmaf(wB.y, (&v[3].x)[k], u);
                u = fmaf(wB.z, (&v[4].x)[k], u);
                u = fmaf(wB.w, (&v[5].x)[k], u);
                u = fmaf(wC.x, (&v[6].x)[k], u);
                u = fmaf(wC.y, (&v[7].x)[k], u);
                a[c][k] = fmaxf(u, 0.0f);
            }
        }

        // Layer 1 (bias folded into first FMA).
        float b[8][4];
        const float4 b1A = *reinterpret_cast<const float4*>(sw + 168);
        const float4 b1B = *reinterpret_cast<const float4*>(sw + 172);
        const float b1v[8] = { b1A.x, b1A.y, b1A.z, b1A.w, b1B.x, b1B.y, b1B.z, b1B.w };
        #pragma unroll
        for (int c = 0; c < 8; ++c) {
            const float4 wA = *reinterpret_cast<const float4*>(sw + 104 + c * 8);
            const float4 wB = *reinterpret_cast<const float4*>(sw + 104 + c * 8 + 4);
            #pragma unroll
            for (int k = 0; k < 4; ++k) {
                float u = fmaf(wA.x, a[0][k], b1v[c]);
                u = fmaf(wA.y, a[1][k], u);
                u = fmaf(wA.z, a[2][k], u);
                u = fmaf(wA.w, a[3][k], u);
                u = fmaf(wB.x, a[4][k], u);
                u = fmaf(wB.y, a[5][k], u);
                u = fmaf(wB.z, a[6][k], u);
                u = fmaf(wB.w, a[7][k], u);
                b[c][k] = fmaxf(u, 0.0f);
            }
        }

        // Layer 2 (weights pre-scaled 0.5 -> half-logits into smem).
        {
            const float4 wA = *reinterpret_cast<const float4*>(sw + 176);
            const float4 wB = *reinterpret_cast<const float4*>(sw + 180);
            const float b2 = sw[184];
            float o[4];
            #pragma unroll
            for (int k = 0; k < 4; ++k) {
                float u = fmaf(wA.x, b[0][k], b2);
                u = fmaf(wA.y, b[1][k], u);
                u = fmaf(wA.z, b[2][k], u);
                u = fmaf(wA.w, b[3][k], u);
                u = fmaf(wB.x, b[4][k], u);
                u = fmaf(wB.y, b[5][k], u);
                u = fmaf(wB.z, b[6][k], u);
                u = fmaf(wB.w, b[7][k], u);
                o[k] = u;
            }
            *reinterpret_cast<float4*>(sL + base) = make_float4(o[0], o[1], o[2], o[3]);
        }
    }
    __syncthreads();

    // ---------------- Phase 2: aligned_bilinear x2 + sigmoid -----------------
    // R5 structure (4 outputs/thread, 60 iters). sL holds h = 0.5*logit:
    //   odd col:  sig_h(n_c)      even col: sig_h(0.5*(n_{c-1} + n_c))
    // vertical blend via w0/w1 on half-logits; cm1 clamp makes the oy==0 /
    // ox4==0 edge cases fall out for free.
    float* ob = out + ((size_t)head * n_inst + inst) * (size_t)(2 * HH * OWw);

    #pragma unroll 1
    for (int it = 0; it < (2 * HH * OWw) / (NTHREADS * 4); ++it) {   // 60 iters
        const int q    = tid + it * NTHREADS;
        const int oy   = q / (OWw / 4);
        const int ox4  = (q - oy * (OWw / 4)) * 4;
        const int c    = ox4 >> 1;
        const int cm1  = (c > 0) ? c - 1 : 0;

        int r0, r1; float w0, w1;
        if (oy & 1)       { r0 = oy >> 1; r1 = r0;     w0 = 1.0f; w1 = 0.0f; }
        else if (oy == 0) { r0 = 0;       r1 = 0;      w0 = 1.0f; w1 = 0.0f; }
        else              { r1 = oy >> 1; r0 = r1 - 1; w0 = 0.5f; w1 = 0.5f; }

        const float* row0 = sL + r0 * WW;
        const float* row1 = sL + r1 * WW;
        const float A = w0 * row0[cm1]   + w1 * row1[cm1];
        const float B = w0 * row0[c]     + w1 * row1[c];
        const float C = w0 * row0[c + 1] + w1 * row1[c + 1];

        float4 v;
        v.x = sig_h(fmaf(0.5f, A, 0.5f * B));   // A==B when ox4==0 (cm1 clamp)
        v.y = sig_h(B);
        v.z = sig_h(fmaf(0.5f, B, 0.5f * C));
        v.w = sig_h(C);

        *reinterpret_cast<float4*>(ob + oy * OWw + ox4) = v;
    }
}

extern "C" void kernel_launch(void* const* d_in, const int* in_sizes, int n_in,
                              void* d_out, int out_size)
{
    const float* feats = (const float*)d_in[0];
    const float* p1    = (const float*)d_in[1];
    const float* p2    = (const float*)d_in[2];
    const float* loc   = (const float*)d_in[3];
    const float* off   = (const float*)d_in[4];
    const int*   imi   = (const int*)  d_in[5];
    const int*   fpn   = (const int*)  d_in[6];
    float* out = (float*)d_out;

    const int n_inst = in_sizes[5];   // 200
    const size_t smem_bytes = (size_t)SMEM_FLOATS * sizeof(float);  // ~62.2 KB

    static bool attr_set = false;
    if (!attr_set) {
        cudaFuncSetAttribute(dmh_kernel,
                             cudaFuncAttributeMaxDynamicSharedMemorySize,
                             (int)smem_bytes);
        attr_set = true;
    }

    dim3 grid(n_inst, 2);             // 400 blocks -> one wave at 3 CTA/SM
    dmh_kernel<<<grid, NTHREADS, smem_bytes>>>(feats, p1, p2, loc, off, imi, fpn, out);
}

// round 8
// speedup vs baseline: 1.1060x; 1.1060x over previous
#include <cuda_runtime.h>

// DynamicMaskHead fused kernel for GB300 (sm_103a), round 8.
// Structural change: pack the TWO HEADS into f32x2 lanes.
//  - weights repacked as {head0_w, head1_w} pairs in smem -> LDS gives packed
//    operands directly (no duplication; weight loads halved per head-pixel)
//  - fma.rn.f32x2 computes both heads' MLPs at once (~25% fewer issue slots)
//  - layer0 input-outer (transposed weights), layer1 channel-outer with
//    layer2 streamed into the dot -> peak live regs ~78, fits 84 (3 CTA/SM)
//  - block = (instance, 48-row slab), 400 blocks = one wave at 3 CTA/SM
//  - smem tile holds packed half-logit pairs {h0,h1}; phase 2 blends stay
//    packed (add/mul.f32x2), unpack only at tanh + per-head STG.128.

#define WW   160
#define OW   320
#define HW   15360
#define NP   169
#define NT   256

// weight-pair layout (u64 pair indices within swp):
//   [0,80)    l0wT: input-major, i*8 + c   (i<10, c<8)
//   [80,88)   l0b
//   [88,152)  l1w:  c*8 + i
//   [152,160) l1b
//   [160,168) l2w (pre-scaled 0.5)
//   [168]     l2b (pre-scaled 0.5)
#define SWPAIRS 169
#define TILE_PAIRS (49 * WW)           // 7840 pairs (49 rows max)
#define SMEM_BYTES ((TILE_PAIRS + SWPAIRS + 1) * 8)

typedef unsigned long long u64;

__device__ __forceinline__ u64 pk(float lo, float hi) {
    u64 r; asm("mov.b64 %0, {%1, %2};" : "=l"(r) : "f"(lo), "f"(hi)); return r;
}
__device__ __forceinline__ void upk(u64 v, float& lo, float& hi) {
    asm("mov.b64 {%0, %1}, %2;" : "=f"(lo), "=f"(hi) : "l"(v));
}
__device__ __forceinline__ u64 ffma2(u64 a, u64 b, u64 c) {
    u64 d; asm("fma.rn.f32x2 %0, %1, %2, %3;" : "=l"(d) : "l"(a), "l"(b), "l"(c)); return d;
}
__device__ __forceinline__ u64 add2(u64 a, u64 b) {
    u64 d; asm("add.rn.f32x2 %0, %1, %2;" : "=l"(d) : "l"(a), "l"(b)); return d;
}
__device__ __forceinline__ u64 mul2(u64 a, u64 b) {
    u64 d; asm("mul.rn.f32x2 %0, %1, %2;" : "=l"(d) : "l"(a), "l"(b)); return d;
}
__device__ __forceinline__ u64 relu2(u64 v) {
    float lo, hi; upk(v, lo, hi);
    return pk(fmaxf(lo, 0.0f), fmaxf(hi, 0.0f));
}
// x = 0.5*logit: sigmoid(L) = 0.5*tanh(0.5L) + 0.5
__device__ __forceinline__ float sig_h(float x) {
    float t;
    asm("tanh.approx.f32 %0, %1;" : "=f"(t) : "f"(x));
    return fmaf(0.5f, t, 0.5f);
}

__global__ __launch_bounds__(NT, 3)
void dmh_kernel(const float* __restrict__ feats,     // [2, 8, 96, 160]
                const float* __restrict__ p1,        // [N, 169]
                const float* __restrict__ p2,        // [N, 169]
                const float* __restrict__ loc,       // [N, 2]
                const float* __restrict__ off,       // [N, 2]
                const int*   __restrict__ imi,       // [N]
                const int*   __restrict__ fpn,       // [N]
                float*       __restrict__ out)       // [2, N, 192, 320]
{
    extern __shared__ u64 smem_u64[];
    u64* sLp = smem_u64;                       // [TILE_PAIRS] packed half-logits
    u64* swp = smem_u64 + TILE_PAIRS;          // [SWPAIRS] weight pairs

    const int tid    = threadIdx.x;
    const int inst   = blockIdx.x;
    const int slab   = blockIdx.y;             // 0 or 1
    const int n_inst = gridDim.x;

    // ---- Repack: interleave head0/head1 weights into pairs ----
    if (tid < NP) {
        float w1 = p1[inst * NP + tid];
        float w2 = p2[inst * NP + tid];
        int d;
        if      (tid < 80)  { const int c = tid / 10; d = (tid - c * 10) * 8 + c; }  // l0 transposed
        else if (tid < 144) { d = 88 + (tid - 80); }
        else if (tid < 152) { d = 160 + (tid - 144); w1 *= 0.5f; w2 *= 0.5f; }
        else if (tid < 160) { d = 80 + (tid - 152); }
        else if (tid < 168) { d = 152 + (tid - 160); }
        else                { d = 168; w1 *= 0.5f; w2 *= 0.5f; }
        swp[d] = pk(w1, w2);
    }

    const int   lvl     = fpn[inst];
    const float inv_soi = 1.0f / (64.0f * (float)(1 << lvl));
    const float lx0 = loc[2 * inst + 0];
    const float ly0 = loc[2 * inst + 1];
    const float lx1 = lx0 + off[2 * inst + 0] * 128.0f;
    const float ly1 = ly0 + off[2 * inst + 1] * 128.0f;
    const float* fb = feats + (size_t)imi[inst] * (8 * HW);
    const float dxs = -8.0f * inv_soi;
    __syncthreads();

    // ---------------- Phase 1: packed MLP, 2 px x 2 heads per iter ----------
    const int ybase = slab ? 47 : 0;
    const int nrows = slab ? 49 : 48;
    const int npx   = nrows * WW;

    #pragma unroll 1
    for (int p = 2 * tid; p < npx; p += 2 * NT) {
        const int rowl = p / WW;
        const int px   = p - rowl * WW;          // even
        const int y    = ybase + rowl;
        const int base = y * WW + px;

        // coordinate pairs {head0, head1}
        const float yc = (float)(y * 8 + 4);
        const float xc = (float)(px * 8 + 4);
        const u64 yp  = pk((ly0 - yc) * inv_soi, (ly1 - yc) * inv_soi);
        const u64 xpA = pk((lx0 - xc) * inv_soi, (lx1 - xc) * inv_soi);
        const u64 xpB = add2(xpA, pk(dxs, dxs));

        // features for the 2 pixels (8 x LDG.64)
        float2 f2[8];
        #pragma unroll
        for (int j = 0; j < 8; ++j)
            f2[j] = *reinterpret_cast<const float2*>(fb + j * HW + base);

        // layer-0 accumulators: bias pairs (4 LDS.128 each)
        u64 a0[8], a1[8];
        {
            const ulonglong2* bp = reinterpret_cast<const ulonglong2*>(swp + 80);
            #pragma unroll
            for (int h = 0; h < 4; ++h) {
                const ulonglong2 b = bp[h];
                a0[2 * h] = b.x; a0[2 * h + 1] = b.y;
                a1[2 * h] = b.x; a1[2 * h + 1] = b.y;
            }
        }

        // layer 0, input-outer over transposed weights
        #define L0STEP(I, XA, XB)                                             \
        {                                                                     \
            const ulonglong2* Wp = reinterpret_cast<const ulonglong2*>(swp + (I) * 8); \
            const ulonglong2 wa = Wp[0], wb = Wp[1], wc = Wp[2], wd = Wp[3];  \
            a0[0] = ffma2(XA, wa.x, a0[0]);  a1[0] = ffma2(XB, wa.x, a1[0]);  \
            a0[1] = ffma2(XA, wa.y, a0[1]);  a1[1] = ffma2(XB, wa.y, a1[1]);  \
            a0[2] = ffma2(XA, wb.x, a0[2]);  a1[2] = ffma2(XB, wb.x, a1[2]);  \
            a0[3] = ffma2(XA, wb.y, a0[3]);  a1[3] = ffma2(XB, wb.y, a1[3]);  \
            a0[4] = ffma2(XA, wc.x, a0[4]);  a1[4] = ffma2(XB, wc.x, a1[4]);  \
            a0[5] = ffma2(XA, wc.y, a0[5]);  a1[5] = ffma2(XB, wc.y, a1[5]);  \
            a0[6] = ffma2(XA, wd.x, a0[6]);  a1[6] = ffma2(XB, wd.x, a1[6]);  \
            a0[7] = ffma2(XA, wd.y, a0[7]);  a1[7] = ffma2(XB, wd.y, a1[7]);  \
        }
        L0STEP(0, xpA, xpB)
        L0STEP(1, yp,  yp)
        #pragma unroll
        for (int j = 0; j < 8; ++j) {
            const u64 fd0 = pk(f2[j].x, f2[j].x);
            const u64 fd1 = pk(f2[j].y, f2[j].y);
            L0STEP(2 + j, fd0, fd1)
        }
        #undef L0STEP

        #pragma unroll
        for (int c = 0; c < 8; ++c) { a0[c] = relu2(a0[c]); a1[c] = relu2(a1[c]); }

        // layer 1 channel-outer, layer 2 streamed into o
        u64 o0 = swp[168], o1 = o0;
        #pragma unroll
        for (int c = 0; c < 8; ++c) {
            const ulonglong2* Wp = reinterpret_cast<const ulonglong2*>(swp + 88 + c * 8);
            const ulonglong2 wa = Wp[0], wb = Wp[1], wc = Wp[2], wd = Wp[3];
            const u64 bias = swp[152 + c];
            u64 b0 = ffma2(a0[0], wa.x, bias);
            u64 b1 = ffma2(a1[0], wa.x, bias);
            b0 = ffma2(a0[1], wa.y, b0);  b1 = ffma2(a1[1], wa.y, b1);
            b0 = ffma2(a0[2], wb.x, b0);  b1 = ffma2(a1[2], wb.x, b1);
            b0 = ffma2(a0[3], wb.y, b0);  b1 = ffma2(a1[3], wb.y, b1);
            b0 = ffma2(a0[4], wc.x, b0);  b1 = ffma2(a1[4], wc.x, b1);
            b0 = ffma2(a0[5], wc.y, b0);  b1 = ffma2(a1[5], wc.y, b1);
            b0 = ffma2(a0[6], wd.x, b0);  b1 = ffma2(a1[6], wd.x, b1);
            b0 = ffma2(a0[7], wd.y, b0);  b1 = ffma2(a1[7], wd.y, b1);
            const u64 w2 = swp[160 + c];
            o0 = ffma2(relu2(b0), w2, o0);
            o1 = ffma2(relu2(b1), w2, o1);
        }

        sLp[rowl * WW + px]     = o0;    // packed {h0, h1} half-logits
        sLp[rowl * WW + px + 1] = o1;
    }
    __syncthreads();

    // ---------------- Phase 2: packed bilinear x2 + sigmoid ------------------
    // S_i = P[rA][i] + P[rB][i]  (rA==rB for odd rows -> S = 2P)
    //   col 4g   : 0.25*(S_{cm1}+S_{c0})     col 4g+1 : 0.5*S_{c0}
    //   col 4g+2 : 0.25*(S_{c0}+S_{c1})      col 4g+3 : 0.5*S_{c1}
    const u64 H = pk(0.5f, 0.5f);
    const u64 Q = pk(0.25f, 0.25f);
    float* ob0 = out + (size_t)inst * (192 * OW);
    float* ob1 = out + ((size_t)n_inst + inst) * (192 * OW);

    #pragma unroll 1
    for (int it = 0; it < 30; ++it) {
        const int q   = tid + it * NT;          // [0, 7680)
        const int oyl = q / 80;                 // 0..95
        const int g   = q - oyl * 80;           // 0..79
        const int oy  = slab * 96 + oyl;

        const int r1  = oy >> 1;
        const int rA  = (oy & 1) ? r1 : ((r1 > 0) ? r1 - 1 : 0);
        const u64* RB = sLp + (r1 - ybase) * WW;
        const u64* RA = sLp + (rA - ybase) * WW;

        const int c0  = 2 * g;
        const int cm1 = (g > 0) ? c0 - 1 : c0;

        const u64 Sm = add2(RA[cm1],    RB[cm1]);
        const u64 S0 = add2(RA[c0],     RB[c0]);
        const u64 S1 = add2(RA[c0 + 1], RB[c0 + 1]);

        const u64 e0 = mul2(add2(Sm, S0), Q);
        const u64 e1 = mul2(S0, H);
        const u64 e2 = mul2(add2(S0, S1), Q);
        const u64 e3 = mul2(S1, H);

        float a0, b0, a1, b1, a2, b2, a3, b3;
        upk(e0, a0, b0); upk(e1, a1, b1); upk(e2, a2, b2); upk(e3, a3, b3);

        float4 v0, v1;
        v0.x = sig_h(a0); v0.y = sig_h(a1); v0.z = sig_h(a2); v0.w = sig_h(a3);
        v1.x = sig_h(b0); v1.y = sig_h(b1); v1.z = sig_h(b2); v1.w = sig_h(b3);

        const int o = oy * OW + 4 * g;
        *reinterpret_cast<float4*>(ob0 + o) = v0;
        *reinterpret_cast<float4*>(ob1 + o) = v1;
    }
}

extern "C" void kernel_launch(void* const* d_in, const int* in_sizes, int n_in,
                              void* d_out, int out_size)
{
    const float* feats = (const float*)d_in[0];
    const float* p1    = (const float*)d_in[1];
    const float* p2    = (const float*)d_in[2];
    const float* loc   = (const float*)d_in[3];
    const float* off   = (const float*)d_in[4];
    const int*   imi   = (const int*)  d_in[5];
    const int*   fpn   = (const int*)  d_in[6];
    float* out = (float*)d_out;

    const int n_inst = in_sizes[5];   // 200

    static bool attr_set = false;
    if (!attr_set) {
        cudaFuncSetAttribute(dmh_kernel,
                             cudaFuncAttributeMaxDynamicSharedMemorySize,
                             (int)SMEM_BYTES);
        attr_set = true;
    }

    dim3 grid(n_inst, 2);             // 400 blocks (inst x slab), one wave @3 CTA/SM
    dmh_kernel<<<grid, NT, SMEM_BYTES>>>(feats, p1, p2, loc, off, imi, fpn, out);
}